// round 15
// baseline (speedup 1.0000x reference)
#include <cuda_runtime.h>
#include <cstdint>

// DIoU loss, HBM-bound streaming reduction (144 MB read, scalar out).
// R15: WARP-LEVEL work stealing, zero barriers in the main loop. R12/R14's
// per-tile __syncthreads phase-aligned all warps of a CTA (load phase /
// compute phase in lockstep -> periodic DRAM request bubbles). Now each
// warp independently steals a 1024-elem batch (atomicAdd+shfl, 4096 total
// atomics) and walks 8 sub-tiles of 128 elems with the proven 12-LDG
// front-batched shape + L2 prefetch of the next sub-tile.

#define EPS 1e-7f
#define UNROLL 4
#define THREADS 256
#define WTILE (32 * UNROLL)        // 128 elems per warp sub-tile
#define BATCH 8                    // sub-tiles per steal -> 1024 elems
#define MAX_BLOCKS 4096

__device__ float g_partials[MAX_BLOCKS];
__device__ unsigned int g_ticket = 0;   // finalize election
__device__ unsigned int g_work = 0;     // dynamic batch ticket

__device__ __forceinline__ float diou_loss(float4 a, float4 b) {
    float area1 = (a.z - a.x) * (a.w - a.y);
    float area2 = (b.z - b.x) * (b.w - b.y);

    float ltx = fmaxf(a.x, b.x);
    float lty = fmaxf(a.y, b.y);
    float rbx = fminf(a.z, b.z);
    float rby = fminf(a.w, b.w);
    float iw = fmaxf(rbx - ltx, 0.0f);
    float ih = fmaxf(rby - lty, 0.0f);
    float inter = iw * ih;
    float uni = area1 + area2 - inter;

    float cltx = fminf(a.x, b.x);
    float clty = fminf(a.y, b.y);
    float crbx = fmaxf(a.z, b.z);
    float crby = fmaxf(a.w, b.w);
    float wc = crbx - cltx;
    float hc = crby - clty;
    float area_c = wc * hc;

    float iou = __fdividef(inter, uni);
    float giou = iou - __fdividef(area_c - uni, area_c);

    float dcx = (a.x + a.z) * 0.5f - (b.x + b.z) * 0.5f;
    float dcy = (a.y + a.w) * 0.5f - (b.y + b.w) * 0.5f;
    float d2 = dcx * dcx + dcy * dcy;
    float diag2 = wc * wc + hc * hc;
    float diou = giou - __fdividef(d2, diag2 + EPS);

    return 1.0f - diou;
}

__device__ __forceinline__ void prefetch_l2(const void* p) {
    asm volatile("prefetch.global.L2 [%0];" :: "l"(p));
}

__global__ void __launch_bounds__(THREADS)
diou_kernel(const float4* __restrict__ boxes1,
            const float4* __restrict__ boxes2,
            const int* __restrict__ mask,
            const int* __restrict__ num_boxes,
            float* __restrict__ out,
            int N, int numBatches) {
    __shared__ float warp_sums[THREADS / 32];
    __shared__ bool is_last;

    int tid = threadIdx.x;
    int lane = tid & 31;
    int wid = tid >> 5;

    float acc = 0.0f;

    // Warp-independent work stealing: no block barriers in this loop.
    while (true) {
        int batch = 0;
        if (lane == 0) batch = (int)atomicAdd(&g_work, 1u);
        batch = __shfl_sync(0xFFFFFFFFu, batch, 0);
        if (batch >= numBatches) break;

        int base0 = batch * (WTILE * BATCH);

        #pragma unroll 1
        for (int s = 0; s < BATCH; s++) {
            int base = base0 + s * WTILE + lane;

            // Front-batched unconditional loads: 12 LDGs in flight.
            float4 a[UNROLL], b[UNROLL];
            int m[UNROLL];
            #pragma unroll
            for (int j = 0; j < UNROLL; j++) {
                int i = base + j * 32;
                a[j] = __ldcs(&boxes1[i]);
                b[j] = __ldcs(&boxes2[i]);
                m[j] = __ldcs(&mask[i]);
            }

            // Prefetch next sub-tile into L2 while these loads are in flight.
            if (s + 1 < BATCH) {
                int pb = base0 + (s + 1) * WTILE + lane;
                #pragma unroll
                for (int j = 0; j < UNROLL; j++) {
                    prefetch_l2(&boxes1[pb + j * 32]);
                    prefetch_l2(&boxes2[pb + j * 32]);
                    prefetch_l2(&mask[pb + j * 32]);
                }
            }

            #pragma unroll
            for (int j = 0; j < UNROLL; j++)
                acc += diou_loss(a[j], b[j]) * (float)(m[j] != 0);
        }
    }

    // Ragged tail beyond full batches (none for N = 4096*1024; safety).
    if (blockIdx.x == 0) {
        for (int i = numBatches * (WTILE * BATCH) + tid; i < N; i += THREADS) {
            float4 a = __ldcs(&boxes1[i]);
            float4 b = __ldcs(&boxes2[i]);
            int m = __ldcs(&mask[i]);
            acc += diou_loss(a, b) * (float)(m != 0);
        }
    }

    // Block reduce.
    #pragma unroll
    for (int off = 16; off > 0; off >>= 1)
        acc += __shfl_down_sync(0xFFFFFFFFu, acc, off);

    if (lane == 0) warp_sums[wid] = acc;
    __syncthreads();

    if (wid == 0) {
        float v = (lane < THREADS / 32) ? warp_sums[lane] : 0.0f;
        #pragma unroll
        for (int off = 4; off > 0; off >>= 1)
            v += __shfl_down_sync(0xFFFFFFFFu, v, off);
        if (lane == 0) {
            g_partials[blockIdx.x] = v;
            __threadfence();
            unsigned int ticket = atomicAdd(&g_ticket, 1u);
            is_last = (ticket == gridDim.x - 1);
        }
    }
    __syncthreads();

    // Last block: reduce partials, write out, reset tickets for next replay.
    if (is_last) {
        float v = 0.0f;
        for (int i = threadIdx.x; i < gridDim.x; i += THREADS)
            v += g_partials[i];
        #pragma unroll
        for (int off = 16; off > 0; off >>= 1)
            v += __shfl_down_sync(0xFFFFFFFFu, v, off);
        if (lane == 0) warp_sums[wid] = v;
        __syncthreads();
        if (wid == 0) {
            float s = (lane < THREADS / 32) ? warp_sums[lane] : 0.0f;
            #pragma unroll
            for (int off = 4; off > 0; off >>= 1)
                s += __shfl_down_sync(0xFFFFFFFFu, s, off);
            if (lane == 0) {
                g_ticket = 0;
                g_work = 0;
                out[0] = s * (1.0f / (float)num_boxes[0]);
            }
        }
    }
}

extern "C" void kernel_launch(void* const* d_in, const int* in_sizes, int n_in,
                              void* d_out, int out_size) {
    const float4* boxes1 = (const float4*)d_in[0];
    const float4* boxes2 = (const float4*)d_in[1];
    const int* mask = (const int*)d_in[2];
    const int* num_boxes = (const int*)d_in[3];
    float* out = (float*)d_out;

    int N = in_sizes[0] / 4;                 // B*Q elements
    int numBatches = N / (WTILE * BATCH);    // 4096 batches of 1024 elems

    // 592 = 148 SMs * 4 CTAs (~55 regs); stealing absorbs any skew.
    int blocks = 148 * 4;
    if (blocks > MAX_BLOCKS) blocks = MAX_BLOCKS;
    if (blocks < 1) blocks = 1;

    diou_kernel<<<blocks, THREADS>>>(boxes1, boxes2, mask, num_boxes, out,
                                     N, numBatches);
}

// round 16
// speedup vs baseline: 1.1635x; 1.1635x over previous
#include <cuda_runtime.h>
#include <cstdint>

// DIoU loss, HBM-bound streaming reduction (144 MB read, scalar out).
// R16: R12 work-stealing champion (UNROLL=4 tile=1024, 12 front-batched
// LDGs, single-launch finalize) with PREFETCH DISTANCE 2: two stolen
// tickets in flight, each tile's L2 prefetch issued ~2 iterations
// (~1400 cyc) before its demand loads, so they land as L2 hits (~240 cyc)
// instead of racing DRAM latency (R12's distance-1 gave only ~600 cyc).

#define EPS 1e-7f
#define UNROLL 4
#define THREADS 256
#define TILE (THREADS * UNROLL)
#define MAX_BLOCKS 4096

__device__ float g_partials[MAX_BLOCKS];
__device__ unsigned int g_ticket = 0;   // finalize election
__device__ unsigned int g_work = 0;     // dynamic tile ticket

__device__ __forceinline__ float diou_loss(float4 a, float4 b) {
    float area1 = (a.z - a.x) * (a.w - a.y);
    float area2 = (b.z - b.x) * (b.w - b.y);

    float ltx = fmaxf(a.x, b.x);
    float lty = fmaxf(a.y, b.y);
    float rbx = fminf(a.z, b.z);
    float rby = fminf(a.w, b.w);
    float iw = fmaxf(rbx - ltx, 0.0f);
    float ih = fmaxf(rby - lty, 0.0f);
    float inter = iw * ih;
    float uni = area1 + area2 - inter;

    float cltx = fminf(a.x, b.x);
    float clty = fminf(a.y, b.y);
    float crbx = fmaxf(a.z, b.z);
    float crby = fmaxf(a.w, b.w);
    float wc = crbx - cltx;
    float hc = crby - clty;
    float area_c = wc * hc;

    float iou = __fdividef(inter, uni);
    float giou = iou - __fdividef(area_c - uni, area_c);

    float dcx = (a.x + a.z) * 0.5f - (b.x + b.z) * 0.5f;
    float dcy = (a.y + a.w) * 0.5f - (b.y + b.w) * 0.5f;
    float d2 = dcx * dcx + dcy * dcy;
    float diag2 = wc * wc + hc * hc;
    float diou = giou - __fdividef(d2, diag2 + EPS);

    return 1.0f - diou;
}

__device__ __forceinline__ void prefetch_l2(const void* p) {
    asm volatile("prefetch.global.L2 [%0];" :: "l"(p));
}

__global__ void __launch_bounds__(THREADS)
diou_kernel(const float4* __restrict__ boxes1,
            const float4* __restrict__ boxes2,
            const int* __restrict__ mask,
            const int* __restrict__ num_boxes,
            float* __restrict__ out,
            int N, int numTiles) {
    __shared__ int s_next;
    __shared__ float warp_sums[THREADS / 32];
    __shared__ bool is_last;

    int tid = threadIdx.x;
    int lane = tid & 31;
    int wid = tid >> 5;

    float acc = 0.0f;

    // Prime: steal tiles t (current) and t1 (next); prefetch t1 now.
    if (tid == 0) s_next = (int)atomicAdd(&g_work, 1u);
    __syncthreads();
    int t = s_next;
    if (tid == 0) s_next = (int)atomicAdd(&g_work, 1u);
    __syncthreads();
    int t1 = s_next;
    if (t1 < numTiles) {
        int pb = t1 * TILE + tid;
        #pragma unroll
        for (int j = 0; j < UNROLL; j++) {
            prefetch_l2(&boxes1[pb + j * THREADS]);
            prefetch_l2(&boxes2[pb + j * THREADS]);
            prefetch_l2(&mask[pb + j * THREADS]);
        }
    }

    while (t < numTiles) {
        // Steal tile t+2 (overlaps with this tile's loads).
        if (tid == 0) s_next = (int)atomicAdd(&g_work, 1u);

        int base = t * TILE + tid;
        // Front-batched unconditional loads: 12 LDGs in flight.
        float4 a[UNROLL], b[UNROLL];
        int m[UNROLL];
        #pragma unroll
        for (int j = 0; j < UNROLL; j++) {
            int i = base + j * THREADS;
            a[j] = __ldcs(&boxes1[i]);
            b[j] = __ldcs(&boxes2[i]);
            m[j] = __ldcs(&mask[i]);
        }

        __syncthreads();  // s_next (t+2) visible to all threads
        int t2 = s_next;

        // Prefetch tile t+2 into L2: lands ~2 iterations before its loads.
        if (t2 < numTiles) {
            int pb = t2 * TILE + tid;
            #pragma unroll
            for (int j = 0; j < UNROLL; j++) {
                prefetch_l2(&boxes1[pb + j * THREADS]);
                prefetch_l2(&boxes2[pb + j * THREADS]);
                prefetch_l2(&mask[pb + j * THREADS]);
            }
        }

        #pragma unroll
        for (int j = 0; j < UNROLL; j++)
            acc += diou_loss(a[j], b[j]) * (float)(m[j] != 0);

        t = t1;
        t1 = t2;
    }

    // Ragged tail beyond full tiles (none for N = 4096*1024; safety).
    if (blockIdx.x == 0) {
        for (int i = numTiles * TILE + tid; i < N; i += THREADS) {
            float4 a = __ldcs(&boxes1[i]);
            float4 b = __ldcs(&boxes2[i]);
            int m = __ldcs(&mask[i]);
            acc += diou_loss(a, b) * (float)(m != 0);
        }
    }

    // Block reduce.
    #pragma unroll
    for (int off = 16; off > 0; off >>= 1)
        acc += __shfl_down_sync(0xFFFFFFFFu, acc, off);

    if (lane == 0) warp_sums[wid] = acc;
    __syncthreads();

    if (wid == 0) {
        float v = (lane < THREADS / 32) ? warp_sums[lane] : 0.0f;
        #pragma unroll
        for (int off = 4; off > 0; off >>= 1)
            v += __shfl_down_sync(0xFFFFFFFFu, v, off);
        if (lane == 0) {
            g_partials[blockIdx.x] = v;
            __threadfence();
            unsigned int ticket = atomicAdd(&g_ticket, 1u);
            is_last = (ticket == gridDim.x - 1);
        }
    }
    __syncthreads();

    // Last block: reduce partials, write out, reset tickets for next replay.
    if (is_last) {
        float v = 0.0f;
        for (int i = threadIdx.x; i < gridDim.x; i += THREADS)
            v += g_partials[i];
        #pragma unroll
        for (int off = 16; off > 0; off >>= 1)
            v += __shfl_down_sync(0xFFFFFFFFu, v, off);
        if (lane == 0) warp_sums[wid] = v;
        __syncthreads();
        if (wid == 0) {
            float s = (lane < THREADS / 32) ? warp_sums[lane] : 0.0f;
            #pragma unroll
            for (int off = 4; off > 0; off >>= 1)
                s += __shfl_down_sync(0xFFFFFFFFu, s, off);
            if (lane == 0) {
                g_ticket = 0;
                g_work = 0;
                out[0] = s * (1.0f / (float)num_boxes[0]);
            }
        }
    }
}

extern "C" void kernel_launch(void* const* d_in, const int* in_sizes, int n_in,
                              void* d_out, int out_size) {
    const float4* boxes1 = (const float4*)d_in[0];
    const float4* boxes2 = (const float4*)d_in[1];
    const int* mask = (const int*)d_in[2];
    const int* num_boxes = (const int*)d_in[3];
    float* out = (float*)d_out;

    int N = in_sizes[0] / 4;   // B*Q elements
    int numTiles = N / TILE;   // 4096 full tiles

    // 592 = 148 SMs * 4 CTAs (~55 regs); stealing absorbs any skew.
    int blocks = 148 * 4;
    if (blocks > MAX_BLOCKS) blocks = MAX_BLOCKS;
    if (blocks < 1) blocks = 1;

    diou_kernel<<<blocks, THREADS>>>(boxes1, boxes2, mask, num_boxes, out,
                                     N, numTiles);
}